// round 4
// baseline (speedup 1.0000x reference)
#include <cuda_runtime.h>
#include <cstdint>

// Problem dims
#define BB      128
#define TT      512
#define UU      128
#define NW      80          // N (window/transcription feature dim)
#define HH      512
#define MM      10
#define IN_DIM  83          // 3 + NW
#define KTOT    595         // IN_DIM + HH
#define GRID    128
#define BLOCK   128
#define OUT_STRIDE 593      // H + NW + 1

// ---------------- device global state (no allocations allowed) ----------------
__device__ float g_hbuf[2 * HH * BB];   // transposed h, double buffered: [buf][j][b]
__device__ float g_wT[NW * BB];         // transposed w: [n][b]
__device__ float g_kappa[BB * MM];
__device__ unsigned int g_bar;

// ---------------- helpers ----------------
__device__ __forceinline__ unsigned long long pack2(float x, float y) {
    unsigned long long r;
    asm("mov.b64 %0, {%1, %2};" : "=l"(r) : "f"(x), "f"(y));
    return r;
}
__device__ __forceinline__ void unpack2(unsigned long long v, float &lo, float &hi) {
    asm("mov.b64 {%0, %1}, %2;" : "=f"(lo), "=f"(hi) : "l"(v));
}
// packed fp32x2 FMA (sm_100+): d = a*b + d, lane-wise
__device__ __forceinline__ void ffma2(unsigned long long &d, unsigned long long a, unsigned long long b) {
    asm("fma.rn.f32x2 %0, %1, %2, %0;" : "+l"(d) : "l"(a), "l"(b));
}
__device__ __forceinline__ float sigf(float x) {
    return __fdividef(1.f, 1.f + __expf(-x));
}

__device__ __forceinline__ void grid_barrier(unsigned int target) {
    __threadfence();              // release all this thread's global writes
    __syncthreads();
    if (threadIdx.x == 0) {
        atomicAdd(&g_bar, 1u);
        volatile unsigned int* vp = &g_bar;
        while (*vp < target) { }
        __threadfence();          // acquire: invalidates stale L1 (CCTL.IVALL)
    }
    __syncthreads();
}

// ---------------- init kernel (reset state every replay) ----------------
__global__ void rnn_init_kernel() {
    int tid = blockIdx.x * blockDim.x + threadIdx.x;
    int nthr = gridDim.x * blockDim.x;
    for (int i = tid; i < 2 * HH * BB; i += nthr) g_hbuf[i] = 0.f;
    for (int i = tid; i < NW * BB;     i += nthr) g_wT[i]   = 0.f;
    for (int i = tid; i < BB * MM;     i += nthr) g_kappa[i] = 0.f;
    if (tid == 0) g_bar = 0u;
}

// ---------------- shared memory layout (dynamic) ----------------
#define OFF_W    0                       // 595*16 floats = 38080 B
#define OFF_WD   38080                   // 512*30 floats = 61440 B
#define OFF_TR   99520                   // 128*80 floats = 40960 B
#define OFF_H    140480                  // 512 floats    = 2048 B
#define OFF_WF   142528                  // 132 floats    = 528 B
#define OFF_YP   143056                  // 120->128 fl   = 512 B
#define OFF_Y    143568                  // 32 floats     = 128 B
#define OFF_BD   143696                  // 32 floats     = 128 B
#define OFF_A    143824                  // 16 floats     = 64 B
#define OFF_BE   143888                  // 16 floats     = 64 B
#define OFF_KA   143952                  // 16 floats     = 64 B
#define OFF_BIAS 144016                  // 16 floats     = 64 B
#define SMEM_BYTES 144080

extern __shared__ char smem_raw[];

__global__ void __launch_bounds__(BLOCK, 1)
rnn_persistent_kernel(const float* __restrict__ strokes,
                      const float* __restrict__ trans,
                      const float* __restrict__ Wx,
                      const float* __restrict__ Wh,
                      const float* __restrict__ bvec,
                      const float* __restrict__ Wd,
                      const float* __restrict__ bd,
                      float* __restrict__ out) {
    float* sW    = (float*)(smem_raw + OFF_W);     // [595][16] weight slice
    float* sWd   = (float*)(smem_raw + OFF_WD);    // [512][30]
    float* sTr   = (float*)(smem_raw + OFF_TR);    // [128][80] transcriptions for batch=blockIdx.x
    float* s_h   = (float*)(smem_raw + OFF_H);     // [512]
    float* s_wf  = (float*)(smem_raw + OFF_WF);    // [129]
    float* s_yp  = (float*)(smem_raw + OFF_YP);    // [120]
    float* s_y   = (float*)(smem_raw + OFF_Y);     // [30]
    float* s_bd  = (float*)(smem_raw + OFF_BD);    // [30]
    float* s_a   = (float*)(smem_raw + OFF_A);     // [10]
    float* s_be  = (float*)(smem_raw + OFF_BE);    // [10]
    float* s_ka  = (float*)(smem_raw + OFF_KA);    // [10]
    float* sBias = (float*)(smem_raw + OFF_BIAS);  // [16]

    const int tid = threadIdx.x;
    const int b   = tid;                 // thread == batch row in GEMM phase
    const int bb  = blockIdx.x;          // CTA == batch row in attention phase
    const int j0  = blockIdx.x * 4;      // owned h-columns [j0, j0+4)

    // ---- one-time staging into SMEM ----
    for (int i = tid; i < KTOT * 16; i += BLOCK) {
        int k = i >> 4, c = i & 15;
        int col = ((c >> 2) << 9) + j0 + (c & 3);   // gate*512 + j0 + jj
        sW[i] = (k < IN_DIM) ? Wx[k * 2048 + col] : Wh[(k - IN_DIM) * 2048 + col];
    }
    if (tid < 16) {
        int col = ((tid >> 2) << 9) + j0 + (tid & 3);
        sBias[tid] = bvec[col];
    }
    for (int i = tid; i < HH * 30; i += BLOCK) sWd[i] = Wd[i];
    if (tid < 30) s_bd[tid] = bd[tid];
    for (int i = tid; i < UU * NW; i += BLOCK) sTr[i] = trans[bb * UU * NW + i];
    __syncthreads();

    float creg0 = 0.f, creg1 = 0.f, creg2 = 0.f, creg3 = 0.f;
    unsigned int tgt = 0;

    for (int t = 0; t < TT; ++t) {
        const float* __restrict__ hin  = g_hbuf + (t & 1) * (HH * BB);
        float* __restrict__       hout = g_hbuf + ((t + 1) & 1) * (HH * BB);

        // =========== Phase A: z = inp@Wx + h@Wh + b for 16 owned columns ===========
        unsigned long long acc0 = pack2(sBias[0],  sBias[1]);
        unsigned long long acc1 = pack2(sBias[2],  sBias[3]);
        unsigned long long acc2 = pack2(sBias[4],  sBias[5]);
        unsigned long long acc3 = pack2(sBias[6],  sBias[7]);
        unsigned long long acc4 = pack2(sBias[8],  sBias[9]);
        unsigned long long acc5 = pack2(sBias[10], sBias[11]);
        unsigned long long acc6 = pack2(sBias[12], sBias[13]);
        unsigned long long acc7 = pack2(sBias[14], sBias[15]);

#define FMA_ROW(rowbase, vv) do {                                          \
        const ulonglong2* wp_ = (const ulonglong2*)(rowbase);              \
        ulonglong2 w0_ = wp_[0], w1_ = wp_[1], w2_ = wp_[2], w3_ = wp_[3]; \
        ffma2(acc0, vv, w0_.x); ffma2(acc1, vv, w0_.y);                    \
        ffma2(acc2, vv, w1_.x); ffma2(acc3, vv, w1_.y);                    \
        ffma2(acc4, vv, w2_.x); ffma2(acc5, vv, w2_.y);                    \
        ffma2(acc6, vv, w3_.x); ffma2(acc7, vv, w3_.y); } while (0)

        // x part (k = 0..2)
        {
            const float* xp = strokes + ((size_t)b * TT + t) * 3;
            float x0 = xp[0], x1 = xp[1], x2 = xp[2];
            FMA_ROW(sW + 0 * 16, pack2(x0, x0));
            FMA_ROW(sW + 1 * 16, pack2(x1, x1));
            FMA_ROW(sW + 2 * 16, pack2(x2, x2));
        }
        // w part (k = 3..82)
        {
            const float* wrow = sW + 3 * 16;
#pragma unroll 4
            for (int k = 0; k < NW; ++k) {
                float v = g_wT[k * BB + b];
                unsigned long long vv = pack2(v, v);
                FMA_ROW(wrow + k * 16, vv);
            }
        }
        // h part (k = 0..511)
        {
            const float* wrow = sW + IN_DIM * 16;
#pragma unroll 4
            for (int k = 0; k < HH; ++k) {
                float v = hin[k * BB + b];
                unsigned long long vv = pack2(v, v);
                FMA_ROW(wrow + k * 16, vv);
            }
        }

        // =========== Phase B: LSTM pointwise update (columns j0..j0+3) ===========
        {
            float z[16];
            unpack2(acc0, z[0],  z[1]);  unpack2(acc1, z[2],  z[3]);
            unpack2(acc2, z[4],  z[5]);  unpack2(acc3, z[6],  z[7]);
            unpack2(acc4, z[8],  z[9]);  unpack2(acc5, z[10], z[11]);
            unpack2(acc6, z[12], z[13]); unpack2(acc7, z[14], z[15]);
            float cn, hn;
            cn = sigf(z[4]) * creg0 + sigf(z[0]) * tanhf(z[8]);
            hn = sigf(z[12]) * tanhf(cn); creg0 = cn;
            hout[(j0 + 0) * BB + b] = hn;
            cn = sigf(z[5]) * creg1 + sigf(z[1]) * tanhf(z[9]);
            hn = sigf(z[13]) * tanhf(cn); creg1 = cn;
            hout[(j0 + 1) * BB + b] = hn;
            cn = sigf(z[6]) * creg2 + sigf(z[2]) * tanhf(z[10]);
            hn = sigf(z[14]) * tanhf(cn); creg2 = cn;
            hout[(j0 + 2) * BB + b] = hn;
            cn = sigf(z[7]) * creg3 + sigf(z[3]) * tanhf(z[11]);
            hn = sigf(z[15]) * tanhf(cn); creg3 = cn;
            hout[(j0 + 3) * BB + b] = hn;
        }

        tgt += GRID;
        grid_barrier(tgt);   // all h_new visible

        // =========== Phase C: attention head for batch row bb ===========
        {
            float* orow = out + ((size_t)bb * TT + t) * OUT_STRIDE;

            // load h row (strided from transposed buf) + emit output h part
            for (int j = tid; j < HH; j += BLOCK) {
                float hv = hout[j * BB + bb];
                s_h[j] = hv;
                orow[j] = hv;
            }
            __syncthreads();

            // y = h @ Wd  (30 outputs, 4-way K split)
            if (tid < 120) {
                int n = tid >> 2, q = tid & 3;
                int k0 = q * 128;
                float p0 = 0.f, p1 = 0.f, p2 = 0.f, p3 = 0.f;
#pragma unroll 4
                for (int k = k0; k < k0 + 128; k += 4) {
                    p0 = fmaf(s_h[k],     sWd[(k)     * 30 + n], p0);
                    p1 = fmaf(s_h[k + 1], sWd[(k + 1) * 30 + n], p1);
                    p2 = fmaf(s_h[k + 2], sWd[(k + 2) * 30 + n], p2);
                    p3 = fmaf(s_h[k + 3], sWd[(k + 3) * 30 + n], p3);
                }
                s_yp[tid] = (p0 + p1) + (p2 + p3);
            }
            __syncthreads();
            if (tid < 30) {
                float s = s_yp[tid * 4] + s_yp[tid * 4 + 1] + s_yp[tid * 4 + 2] + s_yp[tid * 4 + 3];
                s_y[tid] = __expf(s + s_bd[tid]);
            }
            __syncthreads();
            if (tid < MM) {
                float ka = g_kappa[bb * MM + tid] + s_y[20 + tid];
                g_kappa[bb * MM + tid] = ka;
                s_ka[tid] = ka;
                s_a[tid]  = s_y[tid];
                s_be[tid] = s_y[10 + tid];
            }
            __syncthreads();

            // phi / wfull over u = 0..128
            for (int u = tid; u <= UU; u += BLOCK) {
                float fu = (float)u;
                float acc = 0.f;
#pragma unroll
                for (int m = 0; m < MM; ++m) {
                    float d = s_ka[m] - fu;
                    acc = fmaf(s_a[m], __expf(-s_be[m] * d * d), acc);
                }
                s_wf[u] = acc;
            }
            __syncthreads();

            // argmax (first-max tie rule), warp 0
            if (tid < 32) {
                float bv = -3.4e38f; int bi = 0;
                for (int u = tid; u <= UU; u += 32) {
                    float v = s_wf[u];
                    if (v > bv) { bv = v; bi = u; }
                }
                for (int off = 16; off; off >>= 1) {
                    float ov = __shfl_xor_sync(0xffffffffu, bv, off);
                    int   oi = __shfl_xor_sync(0xffffffffu, bi, off);
                    if (ov > bv || (ov == bv && oi < bi)) { bv = ov; bi = oi; }
                }
                if (tid == 0) orow[HH + NW] = (float)bi;
            }

            // w = wfull[:U] @ transcriptions[bb]
            if (tid < NW) {
                float a0 = 0.f, a1 = 0.f, a2 = 0.f, a3 = 0.f;
#pragma unroll 4
                for (int u = 0; u < UU; u += 4) {
                    a0 = fmaf(s_wf[u],     sTr[(u)     * NW + tid], a0);
                    a1 = fmaf(s_wf[u + 1], sTr[(u + 1) * NW + tid], a1);
                    a2 = fmaf(s_wf[u + 2], sTr[(u + 2) * NW + tid], a2);
                    a3 = fmaf(s_wf[u + 3], sTr[(u + 3) * NW + tid], a3);
                }
                float wv = (a0 + a1) + (a2 + a3);
                g_wT[tid * BB + bb] = wv;
                orow[HH + tid] = wv;
            }
        }

        tgt += GRID;
        grid_barrier(tgt);   // w, kappa visible for next step
    }
#undef FMA_ROW
}

// ---------------- launch ----------------
extern "C" void kernel_launch(void* const* d_in, const int* in_sizes, int n_in,
                              void* d_out, int out_size) {
    const float* strokes = (const float*)d_in[0];
    const float* trans   = (const float*)d_in[1];
    // d_in[2] = enumerated (0..128) -- recomputed on the fly
    const float* Wx      = (const float*)d_in[3];
    const float* Wh      = (const float*)d_in[4];
    const float* bvec    = (const float*)d_in[5];
    const float* Wd      = (const float*)d_in[6];
    const float* bd      = (const float*)d_in[7];
    float* out = (float*)d_out;

    cudaFuncSetAttribute(rnn_persistent_kernel,
                         cudaFuncAttributeMaxDynamicSharedMemorySize, SMEM_BYTES);

    rnn_init_kernel<<<32, 256>>>();
    rnn_persistent_kernel<<<GRID, BLOCK, SMEM_BYTES>>>(strokes, trans, Wx, Wh,
                                                       bvec, Wd, bd, out);
}

// round 5
// speedup vs baseline: 1.6612x; 1.6612x over previous
#include <cuda_runtime.h>
#include <cstdint>

// Problem dims
#define BB      128
#define TT      512
#define UU      128
#define NW      80          // N (window/transcription feature dim)
#define HH      512
#define MM      10
#define IN_DIM  83          // 3 + NW
#define KTOT    595         // IN_DIM + HH
#define KSTAGE  592         // w (80) + h (512) staged rows
#define GRID    128
#define BLOCK   256
#define OUT_STRIDE 593      // H + NW + 1
#define CHUNK   64
#define NCHUNK  10          // 9*64 + 16

// ---------------- device global state (no allocations allowed) ----------------
// g_inp[buf][row][b]: rows 0..79 = w^T, rows 80..591 = h^T  (transposed, coalesced in b)
__device__ float g_inp[2 * KSTAGE * BB];
__device__ float g_kappa[BB * MM];
__device__ unsigned int g_bar;

// ---------------- helpers ----------------
__device__ __forceinline__ unsigned long long pack2(float x, float y) {
    unsigned long long r;
    asm("mov.b64 %0, {%1, %2};" : "=l"(r) : "f"(x), "f"(y));
    return r;
}
__device__ __forceinline__ void unpack2(unsigned long long v, float &lo, float &hi) {
    asm("mov.b64 {%0, %1}, %2;" : "=f"(lo), "=f"(hi) : "l"(v));
}
// packed fp32x2 FMA (sm_100+): d = a*b + d, lane-wise
__device__ __forceinline__ void ffma2(unsigned long long &d, unsigned long long a, unsigned long long b) {
    asm("fma.rn.f32x2 %0, %1, %2, %0;" : "+l"(d) : "l"(a), "l"(b));
}
__device__ __forceinline__ float sigf(float x) {
    return __fdividef(1.f, 1.f + __expf(-x));
}

__device__ __forceinline__ void grid_barrier(unsigned int target) {
    __threadfence();              // release all this thread's global writes
    __syncthreads();
    if (threadIdx.x == 0) {
        atomicAdd(&g_bar, 1u);
        volatile unsigned int* vp = &g_bar;
        while (*vp < target) { }
        __threadfence();          // acquire
    }
    __syncthreads();
}

// ---------------- init kernel (reset state every replay) ----------------
__global__ void rnn_init_kernel() {
    int tid = blockIdx.x * blockDim.x + threadIdx.x;
    int nthr = gridDim.x * blockDim.x;
    for (int i = tid; i < 2 * KSTAGE * BB; i += nthr) g_inp[i] = 0.f;
    for (int i = tid; i < BB * MM;        i += nthr) g_kappa[i] = 0.f;
    if (tid == 0) g_bar = 0u;
}

// ---------------- shared memory layout (dynamic) ----------------
#define OFF_W    0                       // 595*16 floats = 38080 B
#define OFF_WD   38080                   // 512*30 floats = 61440 B
#define OFF_TR   99520                   // 128*80 floats = 40960 B
#define OFF_IN   140480                  // 2*64*128 fl   = 65536 B
#define OFF_H    206016                  // 512 floats    = 2048 B
#define OFF_WF   208064                  // 136 floats    = 544 B
#define OFF_YP   208608                  // 240 floats    = 960 B
#define OFF_Y    209568                  // 32 floats     = 128 B
#define OFF_BD   209696                  // 32 floats     = 128 B
#define OFF_A    209824                  // 16 floats     = 64 B
#define OFF_BE   209888                  // 16 floats     = 64 B
#define OFF_KA   209952                  // 16 floats     = 64 B
#define OFF_BIAS 210016                  // 16 floats     = 64 B
#define SMEM_BYTES 210080

extern __shared__ char smem_raw[];

__device__ __forceinline__ void prefetch_chunk(const float* gsrc, uint32_t sdst,
                                               int nf4, int tid) {
    for (int i = tid; i < nf4; i += BLOCK) {
        asm volatile("cp.async.cg.shared.global [%0], [%1], 16;"
                     :: "r"(sdst + i * 16), "l"(gsrc + i * 4));
    }
    asm volatile("cp.async.commit_group;");
}

__global__ void __launch_bounds__(BLOCK, 1)
rnn_persistent_kernel(const float* __restrict__ strokes,
                      const float* __restrict__ trans,
                      const float* __restrict__ Wx,
                      const float* __restrict__ Wh,
                      const float* __restrict__ bvec,
                      const float* __restrict__ Wd,
                      const float* __restrict__ bd,
                      float* __restrict__ out) {
    float* sW    = (float*)(smem_raw + OFF_W);     // [595][16] reordered weight slice
    float* sWd   = (float*)(smem_raw + OFF_WD);    // [512][30]
    float* sTr   = (float*)(smem_raw + OFF_TR);    // [128][80]
    float* sIn   = (float*)(smem_raw + OFF_IN);    // [2][64][128] staging
    float* s_h   = (float*)(smem_raw + OFF_H);     // [512]
    float* s_wf  = (float*)(smem_raw + OFF_WF);    // [129]
    float* s_yp  = (float*)(smem_raw + OFF_YP);    // [240]
    float* s_y   = (float*)(smem_raw + OFF_Y);     // [30]
    float* s_bd  = (float*)(smem_raw + OFF_BD);    // [30]
    float* s_a   = (float*)(smem_raw + OFF_A);     // [10]
    float* s_be  = (float*)(smem_raw + OFF_BE);    // [10]
    float* s_ka  = (float*)(smem_raw + OFF_KA);    // [10]
    float* sBias = (float*)(smem_raw + OFF_BIAS);  // [16]

    const uint32_t sIn32 = (uint32_t)__cvta_generic_to_shared(sIn);

    const int tid = threadIdx.x;
    const int b   = tid & 127;           // batch row (GEMM phase)
    const int hw  = tid >> 7;            // half: 0 or 1 (column pair)
    const int w8  = hw * 8;              // offset into reordered sW row
    const int bb  = blockIdx.x;          // CTA == batch row in attention phase
    const int j0  = blockIdx.x * 4;      // owned h-columns [j0, j0+4)

    // ---- one-time staging into SMEM ----
    // sW row layout: [pair p(2)][gate g(4)][q(2)] -> col = g*512 + j0 + 2p + q
    for (int i = tid; i < KTOT * 16; i += BLOCK) {
        int k = i >> 4, c = i & 15;
        int p = c >> 3, g = (c >> 1) & 3, q = c & 1;
        int col = (g << 9) + j0 + 2 * p + q;
        sW[i] = (k < IN_DIM) ? Wx[k * 2048 + col] : Wh[(k - IN_DIM) * 2048 + col];
    }
    if (tid < 16) {
        int p = tid >> 3, g = (tid >> 1) & 3, q = tid & 1;
        int col = (g << 9) + j0 + 2 * p + q;
        sBias[tid] = bvec[col];
    }
    for (int i = tid; i < HH * 30; i += BLOCK) sWd[i] = Wd[i];
    if (tid < 30) s_bd[tid] = bd[tid];
    for (int i = tid; i < UU * NW; i += BLOCK) sTr[i] = trans[bb * UU * NW + i];
    __syncthreads();

    float creg0 = 0.f, creg1 = 0.f;      // c-state for this thread's 2 columns
    unsigned int tgt = 0;

    for (int t = 0; t < TT; ++t) {
        const float* __restrict__ gin = g_inp + (t & 1) * (KSTAGE * BB);

        // =========== Phase A: z = inp@W + b for 8 owned columns ===========
        unsigned long long acc0 = pack2(sBias[w8 + 0], sBias[w8 + 1]);  // gate i
        unsigned long long acc1 = pack2(sBias[w8 + 2], sBias[w8 + 3]);  // gate f
        unsigned long long acc2 = pack2(sBias[w8 + 4], sBias[w8 + 5]);  // gate g
        unsigned long long acc3 = pack2(sBias[w8 + 6], sBias[w8 + 7]);  // gate o

        // kick x loads early
        const float* xp = strokes + ((size_t)b * TT + t) * 3;
        float x0 = xp[0], x1 = xp[1], x2 = xp[2];

        // prime pipeline: chunks 0 and 1
        prefetch_chunk(gin,              sIn32,         CHUNK * 32, tid);
        prefetch_chunk(gin + CHUNK * BB, sIn32 + 32768, CHUNK * 32, tid);

#define FMA_ROW8(rowbase, vv) do {                                         \
        const ulonglong2* wp_ = (const ulonglong2*)(rowbase);              \
        ulonglong2 w0_ = wp_[0], w1_ = wp_[1];                             \
        ffma2(acc0, vv, w0_.x); ffma2(acc1, vv, w0_.y);                    \
        ffma2(acc2, vv, w1_.x); ffma2(acc3, vv, w1_.y); } while (0)

        // x part (sW rows 0..2)
        FMA_ROW8(sW + 0 * 16 + w8, pack2(x0, x0));
        FMA_ROW8(sW + 1 * 16 + w8, pack2(x1, x1));
        FMA_ROW8(sW + 2 * 16 + w8, pack2(x2, x2));

        // staged part (sW rows 3..594 == g_inp rows 0..591), chunked pipeline
        for (int c = 0; c < NCHUNK; ++c) {
            const int base = c * CHUNK;
            const int rows = (base + CHUNK <= KSTAGE) ? CHUNK : (KSTAGE - base);
            if (c < NCHUNK - 1) asm volatile("cp.async.wait_group 1;");
            else                asm volatile("cp.async.wait_group 0;");
            __syncthreads();

            const float* sc = sIn + (c & 1) * (CHUNK * BB);
            const float* wrow = sW + (3 + base) * 16 + w8;
#pragma unroll 4
            for (int r = 0; r < rows; ++r) {
                float v = sc[r * BB + b];
                unsigned long long vv = pack2(v, v);
                FMA_ROW8(wrow + r * 16, vv);
            }
            __syncthreads();
            if (c + 2 < NCHUNK) {
                const int nb = base + 2 * CHUNK;
                const int nr = (nb + CHUNK <= KSTAGE) ? CHUNK : (KSTAGE - nb);
                prefetch_chunk(gin + nb * BB, sIn32 + (c & 1) * 32768, nr * 32, tid);
            }
        }
#undef FMA_ROW8

        // =========== Phase B: LSTM pointwise update (2 owned columns) ===========
        {
            float zi0, zi1, zf0, zf1, zg0, zg1, zo0, zo1;
            unpack2(acc0, zi0, zi1); unpack2(acc1, zf0, zf1);
            unpack2(acc2, zg0, zg1); unpack2(acc3, zo0, zo1);

            float* ginN = g_inp + ((t + 1) & 1) * (KSTAGE * BB);
            float* orow_b = out + ((size_t)b * TT + t) * OUT_STRIDE;
            int col = j0 + 2 * hw;

            float cn = sigf(zf0) * creg0 + sigf(zi0) * tanhf(zg0);
            float hn = sigf(zo0) * tanhf(cn); creg0 = cn;
            orow_b[col] = hn;
            ginN[(NW + col) * BB + b] = hn;

            cn = sigf(zf1) * creg1 + sigf(zi1) * tanhf(zg1);
            hn = sigf(zo1) * tanhf(cn); creg1 = cn;
            orow_b[col + 1] = hn;
            ginN[(NW + col + 1) * BB + b] = hn;
        }

        tgt += GRID;
        grid_barrier(tgt);   // all h_new visible (in out[] and g_inp next buf)

        // =========== Phase C: attention head for batch row bb ===========
        {
            float* orow = out + ((size_t)bb * TT + t) * OUT_STRIDE;

            // coalesced read of own h row from out
            for (int j = tid; j < HH; j += BLOCK) s_h[j] = orow[j];
            __syncthreads();

            // y = h @ Wd  (30 outputs, 8-way K split over 240 threads)
            if (tid < 240) {
                int n = tid >> 3, q = tid & 7;
                int k0 = q * 64;
                float p0 = 0.f, p1 = 0.f, p2 = 0.f, p3 = 0.f;
#pragma unroll 4
                for (int k = k0; k < k0 + 64; k += 4) {
                    p0 = fmaf(s_h[k],     sWd[(k)     * 30 + n], p0);
                    p1 = fmaf(s_h[k + 1], sWd[(k + 1) * 30 + n], p1);
                    p2 = fmaf(s_h[k + 2], sWd[(k + 2) * 30 + n], p2);
                    p3 = fmaf(s_h[k + 3], sWd[(k + 3) * 30 + n], p3);
                }
                s_yp[tid] = (p0 + p1) + (p2 + p3);
            }
            __syncthreads();
            if (tid < 30) {
                float s = 0.f;
#pragma unroll
                for (int q = 0; q < 8; ++q) s += s_yp[tid * 8 + q];
                s_y[tid] = __expf(s + s_bd[tid]);
            }
            __syncthreads();
            if (tid < MM) {
                float ka = g_kappa[bb * MM + tid] + s_y[20 + tid];
                g_kappa[bb * MM + tid] = ka;
                s_ka[tid] = ka;
                s_a[tid]  = s_y[tid];
                s_be[tid] = s_y[10 + tid];
            }
            __syncthreads();

            // phi / wfull over u = 0..128
            if (tid <= UU) {
                float fu = (float)tid;
                float acc = 0.f;
#pragma unroll
                for (int m = 0; m < MM; ++m) {
                    float d = s_ka[m] - fu;
                    acc = fmaf(s_a[m], __expf(-s_be[m] * d * d), acc);
                }
                s_wf[tid] = acc;
            }
            __syncthreads();

            // argmax (first-max tie rule), warp 0
            if (tid < 32) {
                float bv = -3.4e38f; int bi = 0;
                for (int u = tid; u <= UU; u += 32) {
                    float v = s_wf[u];
                    if (v > bv) { bv = v; bi = u; }
                }
                for (int off = 16; off; off >>= 1) {
                    float ov = __shfl_xor_sync(0xffffffffu, bv, off);
                    int   oi = __shfl_xor_sync(0xffffffffu, bi, off);
                    if (ov > bv || (ov == bv && oi < bi)) { bv = ov; bi = oi; }
                }
                if (tid == 0) orow[HH + NW] = (float)bi;
            }

            // w = wfull[:U] @ transcriptions[bb]
            if (tid < NW) {
                float a0 = 0.f, a1 = 0.f, a2 = 0.f, a3 = 0.f;
#pragma unroll 4
                for (int u = 0; u < UU; u += 4) {
                    a0 = fmaf(s_wf[u],     sTr[(u)     * NW + tid], a0);
                    a1 = fmaf(s_wf[u + 1], sTr[(u + 1) * NW + tid], a1);
                    a2 = fmaf(s_wf[u + 2], sTr[(u + 2) * NW + tid], a2);
                    a3 = fmaf(s_wf[u + 3], sTr[(u + 3) * NW + tid], a3);
                }
                float wv = (a0 + a1) + (a2 + a3);
                g_inp[((t + 1) & 1) * (KSTAGE * BB) + tid * BB + bb] = wv;
                orow[HH + tid] = wv;
            }
        }

        tgt += GRID;
        grid_barrier(tgt);   // w, kappa visible for next step's cp.async
    }
}

// ---------------- launch ----------------
extern "C" void kernel_launch(void* const* d_in, const int* in_sizes, int n_in,
                              void* d_out, int out_size) {
    const float* strokes = (const float*)d_in[0];
    const float* trans   = (const float*)d_in[1];
    // d_in[2] = enumerated (0..128) -- recomputed on the fly
    const float* Wx      = (const float*)d_in[3];
    const float* Wh      = (const float*)d_in[4];
    const float* bvec    = (const float*)d_in[5];
    const float* Wd      = (const float*)d_in[6];
    const float* bd      = (const float*)d_in[7];
    float* out = (float*)d_out;

    cudaFuncSetAttribute(rnn_persistent_kernel,
                         cudaFuncAttributeMaxDynamicSharedMemorySize, SMEM_BYTES);

    rnn_init_kernel<<<32, 256>>>();
    rnn_persistent_kernel<<<GRID, BLOCK, SMEM_BYTES>>>(strokes, trans, Wx, Wh,
                                                       bvec, Wd, bd, out);
}